// round 16
// baseline (speedup 1.0000x reference)
#include <cuda_runtime.h>
#include <cuda_fp16.h>
#include <cstdint>

#define NN 50000
#define NE 800000
#define D1 128
#define MID1 256
#define HIDC 200
#define MID2 400
#define OUTC 2
#define MSG_EPS 1e-7f
#define BN_EPS 1e-5f
#define CEIL(a, b) (((a) + (b) - 1) / (b))

#define F_L2E 1.4426950408889634f
#define F_LN2 0.6931471805599453f
#define EPSL2 (1e-7f * 1.4426950408889634f)

// weight-split buffer offsets
#define WOFF1 0
#define WOFF2 32768
#define WOFF3 83968
#define WTOT  163968

// ---------------- device scratch ----------------
__device__ int g_deg[NN];
__device__ int g_rowstart[NN];
__device__ int g_cursor[NN];
__device__ int g_srcs[NE];
__device__ int g_blocksum[128];
__device__ int g_blockoff[128];
__device__ int g_ctr;  // last-block counter (self-cleaning; zero-init)

__device__ float g_h[(size_t)NN * 400];
__device__ float g_h1[(size_t)NN * 200];
__device__ __half g_ah[(size_t)NN * 256];  // aggregate output (single fp16)
__device__ __half g_bh[WTOT];
__device__ __half g_bl[WTOT];
__device__ float g_bnstat[800];            // [0:400) sum, [400:800) sumsq
__device__ float g_scale[400];
__device__ float g_shift[400];

__device__ __forceinline__ void split_f32(float v, __half& hi, __half& lo) {
    hi = __float2half(v);
    lo = __float2half(v - __half2float(hi));
}

// paired fp16 exp2: one MUFU op for two elements
__device__ __forceinline__ __half2 h2ex2(__half2 x) {
    uint32_t xi = *(uint32_t*)&x, ri;
    asm("ex2.approx.f16x2 %0, %1;" : "=r"(ri) : "r"(xi));
    return *(__half2*)&ri;
}

// ---------------- CSR build (multi-block scan) ----------------
__global__ void k_count(const int* __restrict__ dst) {
    int e = blockIdx.x * blockDim.x + threadIdx.x;
    if (e < NE) atomicAdd(&g_deg[dst[e]], 1);
}

__global__ void k_scan_local() {
    __shared__ int sm[512];
    int tid = threadIdx.x;
    int i = blockIdx.x * 512 + tid;
    int v = (i < NN) ? g_deg[i] : 0;
    sm[tid] = v;
    __syncthreads();
    for (int off = 1; off < 512; off <<= 1) {
        int t = (tid >= off) ? sm[tid - off] : 0;
        __syncthreads();
        sm[tid] += t;
        __syncthreads();
    }
    if (i < NN) g_rowstart[i] = sm[tid] - v;
    if (tid == 511) g_blocksum[blockIdx.x] = sm[511];
}

__global__ void k_scan_top(int nb) {
    __shared__ int sm[128];
    int tid = threadIdx.x;
    int v = (tid < nb) ? g_blocksum[tid] : 0;
    sm[tid] = v;
    __syncthreads();
    for (int off = 1; off < 128; off <<= 1) {
        int t = (tid >= off) ? sm[tid - off] : 0;
        __syncthreads();
        sm[tid] += t;
        __syncthreads();
    }
    if (tid < nb) g_blockoff[tid] = sm[tid] - v;
}

__global__ void k_scan_add() {
    int i = blockIdx.x * blockDim.x + threadIdx.x;
    if (i < NN) {
        int r = g_rowstart[i] + g_blockoff[i >> 9];
        g_rowstart[i] = r;
        g_cursor[i] = r;
    }
}

__global__ void k_fill(const int* __restrict__ src, const int* __restrict__ dst) {
    int e = blockIdx.x * blockDim.x + threadIdx.x;
    if (e < NE) {
        int d = dst[e];
        int pos = atomicAdd(&g_cursor[d], 1);
        g_srcs[pos] = src[e];
    }
}

// ---------------- aggregation: warp-per-node, log2-domain softmax, paired f16 ex2 ----------------
template <int D>
__global__ void k_agg(const float* __restrict__ x, __half* __restrict__ oh) {
    constexpr int C4 = (D + 127) / 128;
    int warp = threadIdx.x >> 5;
    int node = blockIdx.x * (blockDim.x >> 5) + warp;
    if (node >= NN) return;
    int lane = threadIdx.x & 31;

    float S[C4][4], W[C4][4];
#pragma unroll
    for (int c = 0; c < C4; c++)
#pragma unroll
        for (int q = 0; q < 4; q++) { S[c][q] = 0.f; W[c][q] = 0.f; }

    int rs = g_rowstart[node];
    int deg = g_deg[node];

    int j = 0;
    for (; j + 3 < deg; j += 4) {
        int s[4];
#pragma unroll
        for (int e = 0; e < 4; e++) s[e] = g_srcs[rs + j + e];
        float4 v[4][C4];
#pragma unroll
        for (int e = 0; e < 4; e++)
#pragma unroll
            for (int c = 0; c < C4; c++) {
                int ch = c * 128 + 4 * lane;
                if ((D % 128 == 0) || ch < D)
                    v[e][c] = __ldg((const float4*)(x + (size_t)s[e] * D + ch));
            }
#pragma unroll
        for (int e = 0; e < 4; e++)
#pragma unroll
            for (int c = 0; c < C4; c++) {
                int ch = c * 128 + 4 * lane;
                if ((D % 128 == 0) || ch < D) {
                    float m0 = fmaxf(v[e][c].x, 0.f) * F_L2E + EPSL2;
                    float m1 = fmaxf(v[e][c].y, 0.f) * F_L2E + EPSL2;
                    float m2 = fmaxf(v[e][c].z, 0.f) * F_L2E + EPSL2;
                    float m3 = fmaxf(v[e][c].w, 0.f) * F_L2E + EPSL2;
                    __half2 ea = h2ex2(__floats2half2_rn(m0, m1));
                    __half2 eb = h2ex2(__floats2half2_rn(m2, m3));
                    float2 fa = __half22float2(ea);
                    float2 fb = __half22float2(eb);
                    S[c][0] += fa.x; W[c][0] += m0 * fa.x;
                    S[c][1] += fa.y; W[c][1] += m1 * fa.y;
                    S[c][2] += fb.x; W[c][2] += m2 * fb.x;
                    S[c][3] += fb.y; W[c][3] += m3 * fb.y;
                }
            }
    }
    for (; j < deg; j++) {
        int s = g_srcs[rs + j];
#pragma unroll
        for (int c = 0; c < C4; c++) {
            int ch = c * 128 + 4 * lane;
            if ((D % 128 == 0) || ch < D) {
                float4 vv = __ldg((const float4*)(x + (size_t)s * D + ch));
                float m0 = fmaxf(vv.x, 0.f) * F_L2E + EPSL2;
                float m1 = fmaxf(vv.y, 0.f) * F_L2E + EPSL2;
                float m2 = fmaxf(vv.z, 0.f) * F_L2E + EPSL2;
                float m3 = fmaxf(vv.w, 0.f) * F_L2E + EPSL2;
                __half2 ea = h2ex2(__floats2half2_rn(m0, m1));
                __half2 eb = h2ex2(__floats2half2_rn(m2, m3));
                float2 fa = __half22float2(ea);
                float2 fb = __half22float2(eb);
                S[c][0] += fa.x; W[c][0] += m0 * fa.x;
                S[c][1] += fa.y; W[c][1] += m1 * fa.y;
                S[c][2] += fb.x; W[c][2] += m2 * fb.x;
                S[c][3] += fb.y; W[c][3] += m3 * fb.y;
            }
        }
    }

    const float* __restrict__ br = x + (size_t)node * D;
#pragma unroll
    for (int c = 0; c < C4; c++) {
        int ch = c * 128 + 4 * lane;
        if ((D % 128 == 0) || ch < D) {
            float4 b4 = *(const float4*)(br + ch);
            float v0 = (deg > 0 ? (W[c][0] / S[c][0]) * F_LN2 : 0.f) + b4.x;
            float v1 = (deg > 0 ? (W[c][1] / S[c][1]) * F_LN2 : 0.f) + b4.y;
            float v2 = (deg > 0 ? (W[c][2] / S[c][2]) * F_LN2 : 0.f) + b4.z;
            float v3 = (deg > 0 ? (W[c][3] / S[c][3]) * F_LN2 : 0.f) + b4.w;
            __half2 hp0 = __floats2half2_rn(v0, v1);
            __half2 hp1 = __floats2half2_rn(v2, v3);
            uint2 hp;
            hp.x = *(uint32_t*)&hp0;
            hp.y = *(uint32_t*)&hp1;
            *(uint2*)(oh + (size_t)node * D + ch) = hp;
        }
    }
}

// ---------------- one-shot weight split ----------------
__global__ void k_splitw3(const float* __restrict__ w1, const float* __restrict__ w2,
                          const float* __restrict__ w3) {
    int i = blockIdx.x * blockDim.x + threadIdx.x;
    float v;
    if (i < WOFF2) v = w1[i];
    else if (i < WOFF3) v = w2[i - WOFF2];
    else if (i < WTOT) v = w3[i - WOFF3];
    else return;
    __half hh, hl;
    split_f32(v, hh, hl);
    g_bh[i] = hh;
    g_bl[i] = hl;
}

// ---------------- tensor-core GEMM: ldmatrix; ALO/BLO toggle lo-correction MMAs ----------------
#define MMA16816(d0, d1, d2, d3, a0, a1, a2, a3, b0, b1)                              \
    asm volatile(                                                                     \
        "mma.sync.aligned.m16n8k16.row.col.f32.f16.f16.f32 "                          \
        "{%0,%1,%2,%3}, {%4,%5,%6,%7}, {%8,%9}, {%0,%1,%2,%3};"                       \
        : "+f"(d0), "+f"(d1), "+f"(d2), "+f"(d3)                                      \
        : "r"(a0), "r"(a1), "r"(a2), "r"(a3), "r"(b0), "r"(b1))

#define LDSM4(r0, r1, r2, r3, addr)                                                  \
    asm volatile("ldmatrix.sync.aligned.m8n8.x4.shared.b16 {%0,%1,%2,%3}, [%4];"      \
                 : "=r"(r0), "=r"(r1), "=r"(r2), "=r"(r3) : "r"(addr))

#define LDSM2T(r0, r1, addr)                                                         \
    asm volatile("ldmatrix.sync.aligned.m8n8.x2.trans.shared.b16 {%0,%1}, [%2];"      \
                 : "=r"(r0), "=r"(r1) : "r"(addr))

// TA: A from fp32 Af with fused BN+ReLU+hi/lo split (requires ALO).
// ALO: include Al*Bh MMA.  BLO: include Ah*Bl MMA.
// FIN: last block computes g_scale/g_shift from g_bnstat (fused BN finalize).
template <bool STATS, bool RELU, bool TA, bool ALO, bool BLO, bool FIN>
__global__ void __launch_bounds__(256) k_hgemm(
    const __half* __restrict__ Ah,
    const float* __restrict__ Af,
    const __half* __restrict__ Bh, const __half* __restrict__ Bl,
    const float* __restrict__ bias, float* __restrict__ C,
    const float* __restrict__ bng, const float* __restrict__ bnbe,
    int M, int K, int N) {
    __shared__ __half sAh[128][40];
    __shared__ __half sAl[ALO ? 128 : 1][ALO ? 40 : 1];
    __shared__ __half sBh[32][72];
    __shared__ __half sBl[BLO ? 32 : 1][BLO ? 72 : 1];
    __shared__ float spsum[8][32];
    __shared__ float spsq[8][32];

    int tid = threadIdx.x;
    int w = tid >> 5, lane = tid & 31;
    int wy = w >> 1, wx = w & 1;
    int g = lane >> 2, t = lane & 3;
    int m0 = blockIdx.y * 128, n0 = blockIdx.x * 64;

    float acc[2][4][4];
#pragma unroll
    for (int mi = 0; mi < 2; mi++)
#pragma unroll
        for (int ni = 0; ni < 4; ni++)
#pragma unroll
            for (int c = 0; c < 4; c++) acc[mi][ni][c] = 0.f;

    uint4 rAh[2], rAl[2], rBh, rBl;
    int a_r0 = (tid * 2) >> 2, a_k0 = ((tid * 2) & 3) * 8;
    int a_r1 = (tid * 2 + 1) >> 2, a_k1 = ((tid * 2 + 1) & 3) * 8;
    int b_k = tid >> 3;
    int b_n = (tid & 7) * 8;

    auto loadA = [&](int slot, int gm, int gk) {
        if (TA) {
            uint4 h4 = make_uint4(0, 0, 0, 0), l4 = make_uint4(0, 0, 0, 0);
            if (gm < M) {
                float4 f0 = *(const float4*)(Af + (size_t)gm * K + gk);
                float4 f1 = *(const float4*)(Af + (size_t)gm * K + gk + 4);
                float vv[8] = {f0.x, f0.y, f0.z, f0.w, f1.x, f1.y, f1.z, f1.w};
                __half hh[8], hl[8];
#pragma unroll
                for (int i = 0; i < 8; i++) {
                    float s = g_scale[gk + i], sh = g_shift[gk + i];
                    float val = fmaxf(vv[i] * s + sh, 0.f);
                    split_f32(val, hh[i], hl[i]);
                }
                __half2 p;
                p = __halves2half2(hh[0], hh[1]); h4.x = *(uint32_t*)&p;
                p = __halves2half2(hh[2], hh[3]); h4.y = *(uint32_t*)&p;
                p = __halves2half2(hh[4], hh[5]); h4.z = *(uint32_t*)&p;
                p = __halves2half2(hh[6], hh[7]); h4.w = *(uint32_t*)&p;
                p = __halves2half2(hl[0], hl[1]); l4.x = *(uint32_t*)&p;
                p = __halves2half2(hl[2], hl[3]); l4.y = *(uint32_t*)&p;
                p = __halves2half2(hl[4], hl[5]); l4.z = *(uint32_t*)&p;
                p = __halves2half2(hl[6], hl[7]); l4.w = *(uint32_t*)&p;
            }
            rAh[slot] = h4;
            rAl[slot] = l4;
        } else {
            rAh[slot] = make_uint4(0, 0, 0, 0);
            if (gm < M && gk < K)
                rAh[slot] = *(const uint4*)(Ah + (size_t)gm * K + gk);
        }
    };

    auto gload = [&](int k0) {
        loadA(0, m0 + a_r0, k0 + a_k0);
        loadA(1, m0 + a_r1, k0 + a_k1);
        rBh = make_uint4(0, 0, 0, 0); rBl = make_uint4(0, 0, 0, 0);
        int gk = k0 + b_k, gn = n0 + b_n;
        if (gk < K && gn < N) {
            rBh = *(const uint4*)(Bh + (size_t)gk * N + gn);
            if (BLO) rBl = *(const uint4*)(Bl + (size_t)gk * N + gn);
        }
    };
    auto sstore = [&]() {
        *(uint4*)&sAh[a_r0][a_k0] = rAh[0];
        *(uint4*)&sAh[a_r1][a_k1] = rAh[1];
        if (ALO) {
            *(uint4*)&sAl[a_r0][a_k0] = rAl[0];
            *(uint4*)&sAl[a_r1][a_k1] = rAl[1];
        }
        *(uint4*)&sBh[b_k][b_n] = rBh;
        if (BLO) *(uint4*)&sBl[b_k][b_n] = rBl;
    };

    int KT = CEIL(K, 32);
    gload(0);

    int lrow = lane & 15;
    int ksel = (lane >> 4) * 8;

    for (int kt = 0; kt < KT; kt++) {
        sstore();
        __syncthreads();
        if (kt + 1 < KT) gload((kt + 1) * 32);

#pragma unroll
        for (int kc = 0; kc < 2; kc++) {
            int kb = kc * 16;
            uint32_t fah[2][4], fal[2][4];
#pragma unroll
            for (int mi = 0; mi < 2; mi++) {
                int row = wy * 32 + mi * 16 + lrow;
                uint32_t ah_addr = (uint32_t)__cvta_generic_to_shared(&sAh[row][kb + ksel]);
                LDSM4(fah[mi][0], fah[mi][1], fah[mi][2], fah[mi][3], ah_addr);
                if (ALO) {
                    uint32_t al_addr = (uint32_t)__cvta_generic_to_shared(&sAl[row][kb + ksel]);
                    LDSM4(fal[mi][0], fal[mi][1], fal[mi][2], fal[mi][3], al_addr);
                }
            }
            uint32_t fbh[4][2], fbl[4][2];
            int krow = kb + (lane & 15);
#pragma unroll
            for (int ni = 0; ni < 4; ni++) {
                int col = wx * 32 + ni * 8;
                uint32_t bh_addr = (uint32_t)__cvta_generic_to_shared(&sBh[krow][col]);
                LDSM2T(fbh[ni][0], fbh[ni][1], bh_addr);
                if (BLO) {
                    uint32_t bl_addr = (uint32_t)__cvta_generic_to_shared(&sBl[krow][col]);
                    LDSM2T(fbl[ni][0], fbl[ni][1], bl_addr);
                }
            }
#pragma unroll
            for (int mi = 0; mi < 2; mi++)
#pragma unroll
                for (int ni = 0; ni < 4; ni++) {
                    MMA16816(acc[mi][ni][0], acc[mi][ni][1], acc[mi][ni][2], acc[mi][ni][3],
                             fah[mi][0], fah[mi][1], fah[mi][2], fah[mi][3],
                             fbh[ni][0], fbh[ni][1]);
                    if (ALO)
                        MMA16816(acc[mi][ni][0], acc[mi][ni][1], acc[mi][ni][2], acc[mi][ni][3],
                                 fal[mi][0], fal[mi][1], fal[mi][2], fal[mi][3],
                                 fbh[ni][0], fbh[ni][1]);
                    if (BLO)
                        MMA16816(acc[mi][ni][0], acc[mi][ni][1], acc[mi][ni][2], acc[mi][ni][3],
                                 fah[mi][0], fah[mi][1], fah[mi][2], fah[mi][3],
                                 fbl[ni][0], fbl[ni][1]);
                }
        }
        __syncthreads();
    }

    // ---- epilogue ----
    float bj[4][2];
#pragma unroll
    for (int ni = 0; ni < 4; ni++) {
        int cn = n0 + wx * 32 + ni * 8 + 2 * t;
        bj[ni][0] = (cn < N) ? bias[cn] : 0.f;
        bj[ni][1] = (cn + 1 < N) ? bias[cn + 1] : 0.f;
    }
    float colsum[4][2], colsq[4][2];
#pragma unroll
    for (int ni = 0; ni < 4; ni++) {
        colsum[ni][0] = colsum[ni][1] = 0.f;
        colsq[ni][0] = colsq[ni][1] = 0.f;
    }

#pragma unroll
    for (int mi = 0; mi < 2; mi++)
#pragma unroll
        for (int r8 = 0; r8 < 2; r8++) {
            int gm = m0 + wy * 32 + mi * 16 + g + r8 * 8;
            bool rowok = gm < M;
#pragma unroll
            for (int ni = 0; ni < 4; ni++) {
                int cn = n0 + wx * 32 + ni * 8 + 2 * t;
                float v0 = acc[mi][ni][r8 * 2 + 0] + bj[ni][0];
                float v1 = acc[mi][ni][r8 * 2 + 1] + bj[ni][1];
                if (RELU) { v0 = fmaxf(v0, 0.f); v1 = fmaxf(v1, 0.f); }
                if (rowok && cn < N)
                    *(float2*)(C + (size_t)gm * N + cn) = make_float2(v0, v1);
                if (STATS && rowok) {
                    colsum[ni][0] += v0;
                    colsum[ni][1] += v1;
                    colsq[ni][0] += v0 * v0;
                    colsq[ni][1] += v1 * v1;
                }
            }
        }

    if (STATS) {
#pragma unroll
        for (int ni = 0; ni < 4; ni++)
#pragma unroll
            for (int j = 0; j < 2; j++) {
                float s = colsum[ni][j], q = colsq[ni][j];
#pragma unroll
                for (int off = 4; off < 32; off <<= 1) {
                    s += __shfl_xor_sync(0xffffffff, s, off);
                    q += __shfl_xor_sync(0xffffffff, q, off);
                }
                if (lane < 4) {
                    spsum[w][ni * 8 + 2 * lane + j] = s;
                    spsq[w][ni * 8 + 2 * lane + j] = q;
                }
            }
        __syncthreads();
        if (tid < 64) {
            int wxsel = tid >> 5, local = tid & 31;
            float s = 0.f, q = 0.f;
#pragma unroll
            for (int yy = 0; yy < 4; yy++) {
                s += spsum[2 * yy + wxsel][local];
                q += spsq[2 * yy + wxsel][local];
            }
            int cn = n0 + wxsel * 32 + local;
            if (cn < N) {
                atomicAdd(&g_bnstat[cn], s);
                atomicAdd(&g_bnstat[400 + cn], q);
            }
        }

        if (FIN) {
            // last-block BN finalize (replaces k_bn_finalize kernel)
            __shared__ int slast;
            __syncthreads();  // all stat atomics of this block issued
            if (tid == 0) {
                __threadfence();
                int total = gridDim.x * gridDim.y;
                int v = atomicAdd(&g_ctr, 1);
                slast = (v == total - 1) ? 1 : 0;
            }
            __syncthreads();
            if (slast) {
                __threadfence();
                for (int c = tid; c < N; c += blockDim.x) {
                    float su = __ldcg(&g_bnstat[c]);
                    float sq = __ldcg(&g_bnstat[400 + c]);
                    float mu = su * (1.f / NN);
                    float var = sq * (1.f / NN) - mu * mu;
                    float sc = bng[c] * rsqrtf(var + BN_EPS);
                    g_scale[c] = sc;
                    g_shift[c] = bnbe[c] - mu * sc;
                }
                __syncthreads();
                if (tid == 0) {
                    __threadfence();
                    g_ctr = 0;  // self-clean for next layer / next replay
                }
            }
        }
    }
}

// ---------------- final projection ----------------
__global__ void k_out(const float* __restrict__ h, const float* __restrict__ w2,
                      const float* __restrict__ b2, float* __restrict__ out) {
    int warp = threadIdx.x >> 5;
    int row = blockIdx.x * 8 + warp;
    if (row >= NN) return;
    int lane = threadIdx.x & 31;
    const float* __restrict__ hr = h + (size_t)row * MID2;
    float a0 = 0.f, a1 = 0.f;
#pragma unroll
    for (int k = lane; k < MID2; k += 32) {
        float a = fmaxf(hr[k] * g_scale[k] + g_shift[k], 0.f);
        a0 += a * w2[2 * k];
        a1 += a * w2[2 * k + 1];
    }
#pragma unroll
    for (int off = 16; off; off >>= 1) {
        a0 += __shfl_xor_sync(0xffffffff, a0, off);
        a1 += __shfl_xor_sync(0xffffffff, a1, off);
    }
    if (lane == 0) {
        out[2 * row + 0] = fmaxf(a0 + b2[0], 0.f);
        out[2 * row + 1] = fmaxf(a1 + b2[1], 0.f);
    }
}

// ---------------- launcher ----------------
extern "C" void kernel_launch(void* const* d_in, const int* in_sizes, int n_in,
                              void* d_out, int out_size) {
    (void)out_size;
    int ix = -1, iei = -1, ic1w1 = -1, ic1w2 = -1, ic2w1 = -1, ic2w2 = -1,
        ic2b2 = -1, ic1b2 = -1;
    int t256[3] = {-1, -1, -1}, n256 = 0;
    int t400[3] = {-1, -1, -1}, n400 = 0;
    for (int i = 0; i < n_in; i++) {
        switch (in_sizes[i]) {
            case NN * D1:     ix = i; break;
            case 2 * NE:      iei = i; break;
            case D1 * MID1:   ic1w1 = i; break;
            case MID1 * HIDC: ic1w2 = i; break;
            case HIDC * MID2: ic2w1 = i; break;
            case MID2 * OUTC: ic2w2 = i; break;
            case OUTC:        ic2b2 = i; break;
            case HIDC:        ic1b2 = i; break;
            case MID1:        if (n256 < 3) t256[n256++] = i; break;
            case MID2:        if (n400 < 3) t400[n400++] = i; break;
        }
    }
    bool alpha = (iei > ic1w1);
    int ic1b1 = t256[0];
    int ic1g  = alpha ? t256[2] : t256[1];
    int ic1be = alpha ? t256[1] : t256[2];
    int ic2b1 = t400[0];
    int ic2g  = alpha ? t400[2] : t400[1];
    int ic2be = alpha ? t400[1] : t400[2];

    const float* x     = (const float*)d_in[ix];
    const int*   ei    = (const int*)d_in[iei];
    const int*   src   = ei;
    const int*   dst   = ei + NE;
    const float* c1_w1 = (const float*)d_in[ic1w1];
    const float* c1_b1 = (const float*)d_in[ic1b1];
    const float* c1_g  = (const float*)d_in[ic1g];
    const float* c1_be = (const float*)d_in[ic1be];
    const float* c1_w2 = (const float*)d_in[ic1w2];
    const float* c1_b2 = (const float*)d_in[ic1b2];
    const float* c2_w1 = (const float*)d_in[ic2w1];
    const float* c2_b1 = (const float*)d_in[ic2b1];
    const float* c2_g  = (const float*)d_in[ic2g];
    const float* c2_be = (const float*)d_in[ic2be];
    const float* c2_w2 = (const float*)d_in[ic2w2];
    const float* c2_b2 = (const float*)d_in[ic2b2];
    float* out = (float*)d_out;

    float *p_h, *p_h1, *p_bnstat;
    int* p_deg;
    __half *p_ah, *p_bh, *p_bl;
    cudaGetSymbolAddress((void**)&p_h, g_h);
    cudaGetSymbolAddress((void**)&p_h1, g_h1);
    cudaGetSymbolAddress((void**)&p_ah, g_ah);
    cudaGetSymbolAddress((void**)&p_bh, g_bh);
    cudaGetSymbolAddress((void**)&p_bl, g_bl);
    cudaGetSymbolAddress((void**)&p_deg, g_deg);
    cudaGetSymbolAddress((void**)&p_bnstat, g_bnstat);

    const int SCAN_BLOCKS = CEIL(NN, 512);
    const int MT = CEIL(NN, 128);

    // CSR build
    cudaMemsetAsync(p_deg, 0, NN * sizeof(int));
    k_count<<<CEIL(NE, 256), 256>>>(dst);
    k_scan_local<<<SCAN_BLOCKS, 512>>>();
    k_scan_top<<<1, 128>>>(SCAN_BLOCKS);
    k_scan_add<<<CEIL(NN, 256), 256>>>();
    k_fill<<<CEIL(NE, 256), 256>>>(src, dst);

    // ---- layer 1 ----
    k_agg<D1><<<CEIL(NN, 8), 256>>>(x, p_ah);
    k_splitw3<<<CEIL(WTOT, 256), 256>>>(c1_w1, c1_w2, c2_w1);
    cudaMemsetAsync(p_bnstat, 0, 800 * sizeof(float));
    // GEMM1a: STATS + fused BN finalize (last block)
    k_hgemm<true, false, false, false, false, true><<<dim3(CEIL(MID1, 64), MT), 256>>>(
        p_ah, nullptr, p_bh + WOFF1, p_bl + WOFF1, c1_b1, p_h, c1_g, c1_be, NN, D1, MID1);
    // GEMM1b: fused BN on A, full 3-MMA precision
    k_hgemm<false, true, true, true, true, false><<<dim3(CEIL(HIDC, 64), MT), 256>>>(
        nullptr, p_h, p_bh + WOFF2, p_bl + WOFF2, c1_b2, p_h1, nullptr, nullptr, NN, MID1, HIDC);

    // ---- layer 2 ----
    k_agg<HIDC><<<CEIL(NN, 8), 256>>>(p_h1, p_ah);
    cudaMemsetAsync(p_bnstat, 0, 800 * sizeof(float));
    // GEMM2: STATS + fused BN finalize (last block)
    k_hgemm<true, false, false, false, false, true><<<dim3(CEIL(MID2, 64), MT), 256>>>(
        p_ah, nullptr, p_bh + WOFF3, p_bl + WOFF3, c2_b1, p_h, c2_g, c2_be, NN, HIDC, MID2);
    k_out<<<CEIL(NN, 8), 256>>>(p_h, c2_w2, c2_b2, out);
}

// round 17
// speedup vs baseline: 1.0054x; 1.0054x over previous
#include <cuda_runtime.h>
#include <cuda_fp16.h>
#include <cstdint>

#define NN 50000
#define NE 800000
#define D1 128
#define MID1 256
#define HIDC 200
#define MID2 400
#define OUTC 2
#define MSG_EPS 1e-7f
#define BN_EPS 1e-5f
#define CEIL(a, b) (((a) + (b) - 1) / (b))

#define F_L2E 1.4426950408889634f
#define F_LN2 0.6931471805599453f
#define EPSL2 (1e-7f * 1.4426950408889634f)

// weight-split buffer offsets
#define WOFF1 0
#define WOFF2 32768
#define WOFF3 83968
#define WTOT  163968

// ---------------- device scratch ----------------
__device__ int g_deg[NN];
__device__ int g_rowstart[NN];
__device__ int g_cursor[NN];
__device__ int g_srcs[NE];
__device__ int g_blocksum[128];
__device__ int g_blockoff[128];

__device__ float g_h[(size_t)NN * 400];
__device__ float g_h1[(size_t)NN * 200];
__device__ __half g_ah[(size_t)NN * 256];  // aggregate output (single fp16)
__device__ __half g_bh[WTOT];
__device__ __half g_bl[WTOT];
__device__ float g_bnstat[800];            // [0:400) sum, [400:800) sumsq
__device__ float g_scale[400];
__device__ float g_shift[400];

__device__ __forceinline__ void split_f32(float v, __half& hi, __half& lo) {
    hi = __float2half(v);
    lo = __float2half(v - __half2float(hi));
}

// paired fp16 exp2: one MUFU op for two elements
__device__ __forceinline__ __half2 h2ex2(__half2 x) {
    uint32_t xi = *(uint32_t*)&x, ri;
    asm("ex2.approx.f16x2 %0, %1;" : "=r"(ri) : "r"(xi));
    return *(__half2*)&ri;
}

// packed fp32x2 ALU (sm_100+): one issue for two fp32 lanes
__device__ __forceinline__ float2 ffma2(float2 a, float2 b, float2 c) {
    float2 d;
    asm("fma.rn.f32x2 %0, %1, %2, %3;"
        : "=l"(reinterpret_cast<uint64_t&>(d))
        : "l"(reinterpret_cast<uint64_t&>(a)),
          "l"(reinterpret_cast<uint64_t&>(b)),
          "l"(reinterpret_cast<uint64_t&>(c)));
    return d;
}
__device__ __forceinline__ float2 fadd2(float2 a, float2 b) {
    float2 d;
    asm("add.rn.f32x2 %0, %1, %2;"
        : "=l"(reinterpret_cast<uint64_t&>(d))
        : "l"(reinterpret_cast<uint64_t&>(a)),
          "l"(reinterpret_cast<uint64_t&>(b)));
    return d;
}

// ---------------- CSR build (multi-block scan) ----------------
__global__ void k_count(const int* __restrict__ dst) {
    int e = blockIdx.x * blockDim.x + threadIdx.x;
    if (e < NE) atomicAdd(&g_deg[dst[e]], 1);
}

__global__ void k_scan_local() {
    __shared__ int sm[512];
    int tid = threadIdx.x;
    int i = blockIdx.x * 512 + tid;
    int v = (i < NN) ? g_deg[i] : 0;
    sm[tid] = v;
    __syncthreads();
    for (int off = 1; off < 512; off <<= 1) {
        int t = (tid >= off) ? sm[tid - off] : 0;
        __syncthreads();
        sm[tid] += t;
        __syncthreads();
    }
    if (i < NN) g_rowstart[i] = sm[tid] - v;
    if (tid == 511) g_blocksum[blockIdx.x] = sm[511];
}

__global__ void k_scan_top(int nb) {
    __shared__ int sm[128];
    int tid = threadIdx.x;
    int v = (tid < nb) ? g_blocksum[tid] : 0;
    sm[tid] = v;
    __syncthreads();
    for (int off = 1; off < 128; off <<= 1) {
        int t = (tid >= off) ? sm[tid - off] : 0;
        __syncthreads();
        sm[tid] += t;
        __syncthreads();
    }
    if (tid < nb) g_blockoff[tid] = sm[tid] - v;
}

__global__ void k_scan_add() {
    int i = blockIdx.x * blockDim.x + threadIdx.x;
    if (i < NN) {
        int r = g_rowstart[i] + g_blockoff[i >> 9];
        g_rowstart[i] = r;
        g_cursor[i] = r;
    }
}

__global__ void k_fill(const int* __restrict__ src, const int* __restrict__ dst) {
    int e = blockIdx.x * blockDim.x + threadIdx.x;
    if (e < NE) {
        int d = dst[e];
        int pos = atomicAdd(&g_cursor[d], 1);
        g_srcs[pos] = src[e];
    }
}

// ---------------- aggregation: warp-per-node, log2 softmax, f16x2 exp + f32x2 ALU ----------------
template <int D>
__global__ void k_agg(const float* __restrict__ x, __half* __restrict__ oh) {
    constexpr int C4 = (D + 127) / 128;
    int warp = threadIdx.x >> 5;
    int node = blockIdx.x * (blockDim.x >> 5) + warp;
    if (node >= NN) return;
    int lane = threadIdx.x & 31;

    const float2 L2E2 = make_float2(F_L2E, F_L2E);
    const float2 EPS2 = make_float2(EPSL2, EPSL2);

    float2 S[C4][2], W[C4][2];
#pragma unroll
    for (int c = 0; c < C4; c++)
#pragma unroll
        for (int q = 0; q < 2; q++) {
            S[c][q] = make_float2(0.f, 0.f);
            W[c][q] = make_float2(0.f, 0.f);
        }

    int rs = g_rowstart[node];
    int deg = g_deg[node];

    int j = 0;
    for (; j + 3 < deg; j += 4) {
        int s[4];
#pragma unroll
        for (int e = 0; e < 4; e++) s[e] = g_srcs[rs + j + e];
        float4 v[4][C4];
#pragma unroll
        for (int e = 0; e < 4; e++)
#pragma unroll
            for (int c = 0; c < C4; c++) {
                int ch = c * 128 + 4 * lane;
                if ((D % 128 == 0) || ch < D)
                    v[e][c] = __ldg((const float4*)(x + (size_t)s[e] * D + ch));
            }
#pragma unroll
        for (int e = 0; e < 4; e++)
#pragma unroll
            for (int c = 0; c < C4; c++) {
                int ch = c * 128 + 4 * lane;
                if ((D % 128 == 0) || ch < D) {
                    float2 r0 = make_float2(fmaxf(v[e][c].x, 0.f), fmaxf(v[e][c].y, 0.f));
                    float2 r1 = make_float2(fmaxf(v[e][c].z, 0.f), fmaxf(v[e][c].w, 0.f));
                    float2 mp0 = ffma2(r0, L2E2, EPS2);
                    float2 mp1 = ffma2(r1, L2E2, EPS2);
                    __half2 ea = h2ex2(__floats2half2_rn(mp0.x, mp0.y));
                    __half2 eb = h2ex2(__floats2half2_rn(mp1.x, mp1.y));
                    float2 fa = __half22float2(ea);
                    float2 fb = __half22float2(eb);
                    S[c][0] = fadd2(S[c][0], fa);
                    S[c][1] = fadd2(S[c][1], fb);
                    W[c][0] = ffma2(mp0, fa, W[c][0]);
                    W[c][1] = ffma2(mp1, fb, W[c][1]);
                }
            }
    }
    for (; j < deg; j++) {
        int s = g_srcs[rs + j];
#pragma unroll
        for (int c = 0; c < C4; c++) {
            int ch = c * 128 + 4 * lane;
            if ((D % 128 == 0) || ch < D) {
                float4 vv = __ldg((const float4*)(x + (size_t)s * D + ch));
                float2 r0 = make_float2(fmaxf(vv.x, 0.f), fmaxf(vv.y, 0.f));
                float2 r1 = make_float2(fmaxf(vv.z, 0.f), fmaxf(vv.w, 0.f));
                float2 mp0 = ffma2(r0, L2E2, EPS2);
                float2 mp1 = ffma2(r1, L2E2, EPS2);
                __half2 ea = h2ex2(__floats2half2_rn(mp0.x, mp0.y));
                __half2 eb = h2ex2(__floats2half2_rn(mp1.x, mp1.y));
                float2 fa = __half22float2(ea);
                float2 fb = __half22float2(eb);
                S[c][0] = fadd2(S[c][0], fa);
                S[c][1] = fadd2(S[c][1], fb);
                W[c][0] = ffma2(mp0, fa, W[c][0]);
                W[c][1] = ffma2(mp1, fb, W[c][1]);
            }
        }
    }

    const float* __restrict__ br = x + (size_t)node * D;
#pragma unroll
    for (int c = 0; c < C4; c++) {
        int ch = c * 128 + 4 * lane;
        if ((D % 128 == 0) || ch < D) {
            float4 b4 = *(const float4*)(br + ch);
            float v0 = (deg > 0 ? (W[c][0].x / S[c][0].x) * F_LN2 : 0.f) + b4.x;
            float v1 = (deg > 0 ? (W[c][0].y / S[c][0].y) * F_LN2 : 0.f) + b4.y;
            float v2 = (deg > 0 ? (W[c][1].x / S[c][1].x) * F_LN2 : 0.f) + b4.z;
            float v3 = (deg > 0 ? (W[c][1].y / S[c][1].y) * F_LN2 : 0.f) + b4.w;
            __half2 hp0 = __floats2half2_rn(v0, v1);
            __half2 hp1 = __floats2half2_rn(v2, v3);
            uint2 hp;
            hp.x = *(uint32_t*)&hp0;
            hp.y = *(uint32_t*)&hp1;
            *(uint2*)(oh + (size_t)node * D + ch) = hp;
        }
    }
}

// ---------------- one-shot weight split ----------------
__global__ void k_splitw3(const float* __restrict__ w1, const float* __restrict__ w2,
                          const float* __restrict__ w3) {
    int i = blockIdx.x * blockDim.x + threadIdx.x;
    float v;
    if (i < WOFF2) v = w1[i];
    else if (i < WOFF3) v = w2[i - WOFF2];
    else if (i < WTOT) v = w3[i - WOFF3];
    else return;
    __half hh, hl;
    split_f32(v, hh, hl);
    g_bh[i] = hh;
    g_bl[i] = hl;
}

// ---------------- tensor-core GEMM: ldmatrix; ALO/BLO toggle lo-correction MMAs ----------------
#define MMA16816(d0, d1, d2, d3, a0, a1, a2, a3, b0, b1)                              \
    asm volatile(                                                                     \
        "mma.sync.aligned.m16n8k16.row.col.f32.f16.f16.f32 "                          \
        "{%0,%1,%2,%3}, {%4,%5,%6,%7}, {%8,%9}, {%0,%1,%2,%3};"                       \
        : "+f"(d0), "+f"(d1), "+f"(d2), "+f"(d3)                                      \
        : "r"(a0), "r"(a1), "r"(a2), "r"(a3), "r"(b0), "r"(b1))

#define LDSM4(r0, r1, r2, r3, addr)                                                  \
    asm volatile("ldmatrix.sync.aligned.m8n8.x4.shared.b16 {%0,%1,%2,%3}, [%4];"      \
                 : "=r"(r0), "=r"(r1), "=r"(r2), "=r"(r3) : "r"(addr))

#define LDSM2T(r0, r1, addr)                                                         \
    asm volatile("ldmatrix.sync.aligned.m8n8.x2.trans.shared.b16 {%0,%1}, [%2];"      \
                 : "=r"(r0), "=r"(r1) : "r"(addr))

// TA: A from fp32 Af with fused BN+ReLU+hi/lo split (requires ALO).
// ALO: include Al*Bh MMA.  BLO: include Ah*Bl MMA.
template <bool STATS, bool RELU, bool TA, bool ALO, bool BLO>
__global__ void __launch_bounds__(256) k_hgemm(
    const __half* __restrict__ Ah,
    const float* __restrict__ Af,
    const __half* __restrict__ Bh, const __half* __restrict__ Bl,
    const float* __restrict__ bias, float* __restrict__ C,
    int M, int K, int N) {
    __shared__ __half sAh[128][40];
    __shared__ __half sAl[ALO ? 128 : 1][ALO ? 40 : 1];
    __shared__ __half sBh[32][72];
    __shared__ __half sBl[BLO ? 32 : 1][BLO ? 72 : 1];
    __shared__ float spsum[8][32];
    __shared__ float spsq[8][32];

    int tid = threadIdx.x;
    int w = tid >> 5, lane = tid & 31;
    int wy = w >> 1, wx = w & 1;
    int g = lane >> 2, t = lane & 3;
    int m0 = blockIdx.y * 128, n0 = blockIdx.x * 64;

    float acc[2][4][4];
#pragma unroll
    for (int mi = 0; mi < 2; mi++)
#pragma unroll
        for (int ni = 0; ni < 4; ni++)
#pragma unroll
            for (int c = 0; c < 4; c++) acc[mi][ni][c] = 0.f;

    uint4 rAh[2], rAl[2], rBh, rBl;
    int a_r0 = (tid * 2) >> 2, a_k0 = ((tid * 2) & 3) * 8;
    int a_r1 = (tid * 2 + 1) >> 2, a_k1 = ((tid * 2 + 1) & 3) * 8;
    int b_k = tid >> 3;
    int b_n = (tid & 7) * 8;

    auto loadA = [&](int slot, int gm, int gk) {
        if (TA) {
            uint4 h4 = make_uint4(0, 0, 0, 0), l4 = make_uint4(0, 0, 0, 0);
            if (gm < M) {
                float4 f0 = *(const float4*)(Af + (size_t)gm * K + gk);
                float4 f1 = *(const float4*)(Af + (size_t)gm * K + gk + 4);
                float vv[8] = {f0.x, f0.y, f0.z, f0.w, f1.x, f1.y, f1.z, f1.w};
                __half hh[8], hl[8];
#pragma unroll
                for (int i = 0; i < 8; i++) {
                    float s = g_scale[gk + i], sh = g_shift[gk + i];
                    float val = fmaxf(vv[i] * s + sh, 0.f);
                    split_f32(val, hh[i], hl[i]);
                }
                __half2 p;
                p = __halves2half2(hh[0], hh[1]); h4.x = *(uint32_t*)&p;
                p = __halves2half2(hh[2], hh[3]); h4.y = *(uint32_t*)&p;
                p = __halves2half2(hh[4], hh[5]); h4.z = *(uint32_t*)&p;
                p = __halves2half2(hh[6], hh[7]); h4.w = *(uint32_t*)&p;
                p = __halves2half2(hl[0], hl[1]); l4.x = *(uint32_t*)&p;
                p = __halves2half2(hl[2], hl[3]); l4.y = *(uint32_t*)&p;
                p = __halves2half2(hl[4], hl[5]); l4.z = *(uint32_t*)&p;
                p = __halves2half2(hl[6], hl[7]); l4.w = *(uint32_t*)&p;
            }
            rAh[slot] = h4;
            rAl[slot] = l4;
        } else {
            rAh[slot] = make_uint4(0, 0, 0, 0);
            if (gm < M && gk < K)
                rAh[slot] = *(const uint4*)(Ah + (size_t)gm * K + gk);
        }
    };

    auto gload = [&](int k0) {
        loadA(0, m0 + a_r0, k0 + a_k0);
        loadA(1, m0 + a_r1, k0 + a_k1);
        rBh = make_uint4(0, 0, 0, 0); rBl = make_uint4(0, 0, 0, 0);
        int gk = k0 + b_k, gn = n0 + b_n;
        if (gk < K && gn < N) {
            rBh = *(const uint4*)(Bh + (size_t)gk * N + gn);
            if (BLO) rBl = *(const uint4*)(Bl + (size_t)gk * N + gn);
        }
    };
    auto sstore = [&]() {
        *(uint4*)&sAh[a_r0][a_k0] = rAh[0];
        *(uint4*)&sAh[a_r1][a_k1] = rAh[1];
        if (ALO) {
            *(uint4*)&sAl[a_r0][a_k0] = rAl[0];
            *(uint4*)&sAl[a_r1][a_k1] = rAl[1];
        }
        *(uint4*)&sBh[b_k][b_n] = rBh;
        if (BLO) *(uint4*)&sBl[b_k][b_n] = rBl;
    };

    int KT = CEIL(K, 32);
    gload(0);

    int lrow = lane & 15;
    int ksel = (lane >> 4) * 8;

    for (int kt = 0; kt < KT; kt++) {
        sstore();
        __syncthreads();
        if (kt + 1 < KT) gload((kt + 1) * 32);

#pragma unroll
        for (int kc = 0; kc < 2; kc++) {
            int kb = kc * 16;
            uint32_t fah[2][4], fal[2][4];
#pragma unroll
            for (int mi = 0; mi < 2; mi++) {
                int row = wy * 32 + mi * 16 + lrow;
                uint32_t ah_addr = (uint32_t)__cvta_generic_to_shared(&sAh[row][kb + ksel]);
                LDSM4(fah[mi][0], fah[mi][1], fah[mi][2], fah[mi][3], ah_addr);
                if (ALO) {
                    uint32_t al_addr = (uint32_t)__cvta_generic_to_shared(&sAl[row][kb + ksel]);
                    LDSM4(fal[mi][0], fal[mi][1], fal[mi][2], fal[mi][3], al_addr);
                }
            }
            uint32_t fbh[4][2], fbl[4][2];
            int krow = kb + (lane & 15);
#pragma unroll
            for (int ni = 0; ni < 4; ni++) {
                int col = wx * 32 + ni * 8;
                uint32_t bh_addr = (uint32_t)__cvta_generic_to_shared(&sBh[krow][col]);
                LDSM2T(fbh[ni][0], fbh[ni][1], bh_addr);
                if (BLO) {
                    uint32_t bl_addr = (uint32_t)__cvta_generic_to_shared(&sBl[krow][col]);
                    LDSM2T(fbl[ni][0], fbl[ni][1], bl_addr);
                }
            }
#pragma unroll
            for (int mi = 0; mi < 2; mi++)
#pragma unroll
                for (int ni = 0; ni < 4; ni++) {
                    MMA16816(acc[mi][ni][0], acc[mi][ni][1], acc[mi][ni][2], acc[mi][ni][3],
                             fah[mi][0], fah[mi][1], fah[mi][2], fah[mi][3],
                             fbh[ni][0], fbh[ni][1]);
                    if (ALO)
                        MMA16816(acc[mi][ni][0], acc[mi][ni][1], acc[mi][ni][2], acc[mi][ni][3],
                                 fal[mi][0], fal[mi][1], fal[mi][2], fal[mi][3],
                                 fbh[ni][0], fbh[ni][1]);
                    if (BLO)
                        MMA16816(acc[mi][ni][0], acc[mi][ni][1], acc[mi][ni][2], acc[mi][ni][3],
                                 fah[mi][0], fah[mi][1], fah[mi][2], fah[mi][3],
                                 fbl[ni][0], fbl[ni][1]);
                }
        }
        __syncthreads();
    }

    // ---- epilogue ----
    float bj[4][2];
#pragma unroll
    for (int ni = 0; ni < 4; ni++) {
        int cn = n0 + wx * 32 + ni * 8 + 2 * t;
        bj[ni][0] = (cn < N) ? bias[cn] : 0.f;
        bj[ni][1] = (cn + 1 < N) ? bias[cn + 1] : 0.f;
    }
    float colsum[4][2], colsq[4][2];
#pragma unroll
    for (int ni = 0; ni < 4; ni++) {
        colsum[ni][0] = colsum[ni][1] = 0.f;
        colsq[ni][0] = colsq[ni][1] = 0.f;
    }

#pragma unroll
    for (int mi = 0; mi < 2; mi++)
#pragma unroll
        for (int r8 = 0; r8 < 2; r8++) {
            int gm = m0 + wy * 32 + mi * 16 + g + r8 * 8;
            bool rowok = gm < M;
#pragma unroll
            for (int ni = 0; ni < 4; ni++) {
                int cn = n0 + wx * 32 + ni * 8 + 2 * t;
                float v0 = acc[mi][ni][r8 * 2 + 0] + bj[ni][0];
                float v1 = acc[mi][ni][r8 * 2 + 1] + bj[ni][1];
                if (RELU) { v0 = fmaxf(v0, 0.f); v1 = fmaxf(v1, 0.f); }
                if (rowok && cn < N)
                    *(float2*)(C + (size_t)gm * N + cn) = make_float2(v0, v1);
                if (STATS && rowok) {
                    colsum[ni][0] += v0;
                    colsum[ni][1] += v1;
                    colsq[ni][0] += v0 * v0;
                    colsq[ni][1] += v1 * v1;
                }
            }
        }

    if (STATS) {
#pragma unroll
        for (int ni = 0; ni < 4; ni++)
#pragma unroll
            for (int j = 0; j < 2; j++) {
                float s = colsum[ni][j], q = colsq[ni][j];
#pragma unroll
                for (int off = 4; off < 32; off <<= 1) {
                    s += __shfl_xor_sync(0xffffffff, s, off);
                    q += __shfl_xor_sync(0xffffffff, q, off);
                }
                if (lane < 4) {
                    spsum[w][ni * 8 + 2 * lane + j] = s;
                    spsq[w][ni * 8 + 2 * lane + j] = q;
                }
            }
        __syncthreads();
        if (tid < 64) {
            int wxsel = tid >> 5, local = tid & 31;
            float s = 0.f, q = 0.f;
#pragma unroll
            for (int yy = 0; yy < 4; yy++) {
                s += spsum[2 * yy + wxsel][local];
                q += spsq[2 * yy + wxsel][local];
            }
            int cn = n0 + wxsel * 32 + local;
            if (cn < N) {
                atomicAdd(&g_bnstat[cn], s);
                atomicAdd(&g_bnstat[400 + cn], q);
            }
        }
    }
}

// ---------------- BN finalize ----------------
__global__ void k_bn_finalize(const float* __restrict__ g, const float* __restrict__ be, int mid) {
    int c = threadIdx.x;
    if (c < mid) {
        float mu = g_bnstat[c] * (1.f / NN);
        float var = g_bnstat[400 + c] * (1.f / NN) - mu * mu;
        float sc = g[c] * rsqrtf(var + BN_EPS);
        g_scale[c] = sc;
        g_shift[c] = be[c] - mu * sc;
    }
}

// ---------------- final projection ----------------
__global__ void k_out(const float* __restrict__ h, const float* __restrict__ w2,
                      const float* __restrict__ b2, float* __restrict__ out) {
    int warp = threadIdx.x >> 5;
    int row = blockIdx.x * 8 + warp;
    if (row >= NN) return;
    int lane = threadIdx.x & 31;
    const float* __restrict__ hr = h + (size_t)row * MID2;
    float a0 = 0.f, a1 = 0.f;
#pragma unroll
    for (int k = lane; k < MID2; k += 32) {
        float a = fmaxf(hr[k] * g_scale[k] + g_shift[k], 0.f);
        a0 += a * w2[2 * k];
        a1 += a * w2[2 * k + 1];
    }
#pragma unroll
    for (int off = 16; off; off >>= 1) {
        a0 += __shfl_xor_sync(0xffffffff, a0, off);
        a1 += __shfl_xor_sync(0xffffffff, a1, off);
    }
    if (lane == 0) {
        out[2 * row + 0] = fmaxf(a0 + b2[0], 0.f);
        out[2 * row + 1] = fmaxf(a1 + b2[1], 0.f);
    }
}

// ---------------- launcher ----------------
extern "C" void kernel_launch(void* const* d_in, const int* in_sizes, int n_in,
                              void* d_out, int out_size) {
    (void)out_size;
    int ix = -1, iei = -1, ic1w1 = -1, ic1w2 = -1, ic2w1 = -1, ic2w2 = -1,
        ic2b2 = -1, ic1b2 = -1;
    int t256[3] = {-1, -1, -1}, n256 = 0;
    int t400[3] = {-1, -1, -1}, n400 = 0;
    for (int i = 0; i < n_in; i++) {
        switch (in_sizes[i]) {
            case NN * D1:     ix = i; break;
            case 2 * NE:      iei = i; break;
            case D1 * MID1:   ic1w1 = i; break;
            case MID1 * HIDC: ic1w2 = i; break;
            case HIDC * MID2: ic2w1 = i; break;
            case MID2 * OUTC: ic2w2 = i; break;
            case OUTC:        ic2b2 = i; break;
            case HIDC:        ic1b2 = i; break;
            case MID1:        if (n256 < 3) t256[n256++] = i; break;
            case MID2:        if (n400 < 3) t400[n400++] = i; break;
        }
    }
    bool alpha = (iei > ic1w1);
    int ic1b1 = t256[0];
    int ic1g  = alpha ? t256[2] : t256[1];
    int ic1be = alpha ? t256[1] : t256[2];
    int ic2b1 = t400[0];
    int ic2g  = alpha ? t400[2] : t400[1];
    int ic2be = alpha ? t400[1] : t400[2];

    const float* x     = (const float*)d_in[ix];
    const int*   ei    = (const int*)d_in[iei];
    const int*   src   = ei;
    const int*   dst   = ei + NE;
    const float* c1_w1 = (const float*)d_in[ic1w1];
    const float* c1_b1 = (const float*)d_in[ic1b1];
    const float* c1_g  = (const float*)d_in[ic1g];
    const float* c1_be = (const float*)d_in[ic1be];
    const float* c1_w2 = (const float*)d_in[ic1w2];
    const float* c1_b2 = (const float*)d_in[ic1b2];
    const float* c2_w1 = (const float*)d_in[ic2w1];
    const float* c2_b1 = (const float*)d_in[ic2b1];
    const float* c2_g  = (const float*)d_in[ic2g];
    const float* c2_be = (const float*)d_in[ic2be];
    const float* c2_w2 = (const float*)d_in[ic2w2];
    const float* c2_b2 = (const float*)d_in[ic2b2];
    float* out = (float*)d_out;

    float *p_h, *p_h1, *p_bnstat;
    int* p_deg;
    __half *p_ah, *p_bh, *p_bl;
    cudaGetSymbolAddress((void**)&p_h, g_h);
    cudaGetSymbolAddress((void**)&p_h1, g_h1);
    cudaGetSymbolAddress((void**)&p_ah, g_ah);
    cudaGetSymbolAddress((void**)&p_bh, g_bh);
    cudaGetSymbolAddress((void**)&p_bl, g_bl);
    cudaGetSymbolAddress((void**)&p_deg, g_deg);
    cudaGetSymbolAddress((void**)&p_bnstat, g_bnstat);

    const int SCAN_BLOCKS = CEIL(NN, 512);
    const int MT = CEIL(NN, 128);

    // CSR build
    cudaMemsetAsync(p_deg, 0, NN * sizeof(int));
    k_count<<<CEIL(NE, 256), 256>>>(dst);
    k_scan_local<<<SCAN_BLOCKS, 512>>>();
    k_scan_top<<<1, 128>>>(SCAN_BLOCKS);
    k_scan_add<<<CEIL(NN, 256), 256>>>();
    k_fill<<<CEIL(NE, 256), 256>>>(src, dst);

    // ---- layer 1 ----
    k_agg<D1><<<CEIL(NN, 8), 256>>>(x, p_ah);
    k_splitw3<<<CEIL(WTOT, 256), 256>>>(c1_w1, c1_w2, c2_w1);
    cudaMemsetAsync(p_bnstat, 0, 800 * sizeof(float));
    k_hgemm<true, false, false, false, false><<<dim3(CEIL(MID1, 64), MT), 256>>>(
        p_ah, nullptr, p_bh + WOFF1, p_bl + WOFF1, c1_b1, p_h, NN, D1, MID1);
    k_bn_finalize<<<1, 512>>>(c1_g, c1_be, MID1);
    k_hgemm<false, true, true, true, true><<<dim3(CEIL(HIDC, 64), MT), 256>>>(
        nullptr, p_h, p_bh + WOFF2, p_bl + WOFF2, c1_b2, p_h1, NN, MID1, HIDC);

    // ---- layer 2 ----
    k_agg<HIDC><<<CEIL(NN, 8), 256>>>(p_h1, p_ah);
    cudaMemsetAsync(p_bnstat, 0, 800 * sizeof(float));
    k_hgemm<true, false, false, false, false><<<dim3(CEIL(MID2, 64), MT), 256>>>(
        p_ah, nullptr, p_bh + WOFF3, p_bl + WOFF3, c2_b1, p_h, NN, HIDC, MID2);
    k_bn_finalize<<<1, 512>>>(c2_g, c2_be, MID2);
    k_out<<<CEIL(NN, 8), 256>>>(p_h, c2_w2, c2_b2, out);
}